// round 17
// baseline (speedup 1.0000x reference)
#include <cuda_runtime.h>
#include <cuda_bf16.h>
#include <math.h>
#include <float.h>
#include <cstdint>

#define B_  2
#define L_  2048
#define D_  1024
#define H_  16
#define DH  64
#define BL  (B_*L_)     // 4096
#define E3  (3*D_)      // 3072

// ---- scratch (static device globals; no allocation allowed) ----
__device__ float    g_qkv[(size_t)BL * E3];      // raw qkv (fp32)
__device__ uint32_t g_qhl[(size_t)B_*H_*L_*64];  // Q bf16 hi/lo packed, pre-scaled
__device__ uint32_t g_khl[(size_t)B_*H_*L_*64];  // K bf16 hi/lo packed
__device__ float    g_v[(size_t)B_*H_*L_*DH];    // V fp32 [bh][l][d]
__device__ uint32_t g_vhl[(size_t)B_*H_*64*(L_)];// V^T bf16 hi/lo packed [bh][d][l-words]
__device__ float    g_ao[(size_t)BL * D_];       // attention out, tf32-rounded
__device__ float    g_xc[(size_t)BL * D_];       // x    tf32-rounded
__device__ float    g_wq[(size_t)E3 * D_];       // Wqkv tf32-rounded
__device__ float    g_wo[(size_t)D_ * D_];       // Wout tf32-rounded

__device__ __forceinline__ uint32_t f2tf32(float x) {
    uint32_t r;
    asm("cvt.rna.tf32.f32 %0, %1;" : "=r"(r) : "f"(x));
    return r;
}
__device__ __forceinline__ float tfv(float x) { return __uint_as_float(f2tf32(x)); }

__device__ __forceinline__ uint32_t smem_u32(const void* p) {
    uint32_t a;
    asm("{ .reg .u64 t; cvta.to.shared.u64 t, %1; cvt.u32.u64 %0, t; }" : "=r"(a) : "l"(p));
    return a;
}

__device__ __forceinline__ void mma_tf32(float* d, const uint32_t* a, const uint32_t* b) {
    asm volatile(
        "mma.sync.aligned.m16n8k8.row.col.f32.tf32.tf32.f32 "
        "{%0,%1,%2,%3}, {%4,%5,%6,%7}, {%8,%9}, {%0,%1,%2,%3};"
        : "+f"(d[0]), "+f"(d[1]), "+f"(d[2]), "+f"(d[3])
        : "r"(a[0]), "r"(a[1]), "r"(a[2]), "r"(a[3]), "r"(b[0]), "r"(b[1]));
}

__device__ __forceinline__ void mma_bf16(float* d, const uint32_t* a, const uint32_t* b) {
    asm volatile(
        "mma.sync.aligned.m16n8k16.row.col.f32.bf16.bf16.f32 "
        "{%0,%1,%2,%3}, {%4,%5,%6,%7}, {%8,%9}, {%0,%1,%2,%3};"
        : "+f"(d[0]), "+f"(d[1]), "+f"(d[2]), "+f"(d[3])
        : "r"(a[0]), "r"(a[1]), "r"(a[2]), "r"(a[3]), "r"(b[0]), "r"(b[1]));
}

// pack {e_lo -> bits[0:16), e_hi -> bits[16:32)}  (rn rounding)
__device__ __forceinline__ uint32_t packbf(float e_lo, float e_hi) {
    uint32_t r;
    asm("cvt.rn.bf16x2.f32 %0, %1, %2;" : "=r"(r) : "f"(e_hi), "f"(e_lo));
    return r;
}
__device__ __forceinline__ float bfv(float x) {
    return __bfloat162float(__float2bfloat16_rn(x));
}

#define LDSM4(rr, addr) \
    asm volatile("ldmatrix.sync.aligned.m8n8.x4.shared.b16 {%0,%1,%2,%3}, [%4];" \
        : "=r"((rr)[0]), "=r"((rr)[1]), "=r"((rr)[2]), "=r"((rr)[3]) : "r"(addr))

#define CPA16(dst, src) \
    asm volatile("cp.async.ca.shared.global [%0], [%1], 16;" :: "r"(dst), "l"(src))
#define CPCOMMIT() asm volatile("cp.async.commit_group;")

// ============================================================
// tf32 pre-conversion
// ============================================================
__global__ __launch_bounds__(256) void conv_tf32(const float4* __restrict__ src,
                                                 float4* __restrict__ dst, int n4) {
    int i = blockIdx.x * blockDim.x + threadIdx.x;
    if (i < n4) {
        float4 v = src[i];
        dst[i] = make_float4(tfv(v.x), tfv(v.y), tfv(v.z), tfv(v.w));
    }
}

// ============================================================
// cp.async pipelined tf32 GEMM, templated N-tile (256 or 128).
// C[M,N] = A[M,K] * Bm[N,K]^T, inputs already tf32-rounded.
// 256 threads (8 warps 2x4), KT=16, 4 stages, ldmatrix fragments.
// ============================================================
#define GKT 16
#define GAST 20
#define ASTG (128*GAST)

template<int BN, int MINCTA>
__global__ __launch_bounds__(256, MINCTA) void gemm_ca(const float* __restrict__ A,
                                                       const float* __restrict__ Bm,
                                                       float* __restrict__ C,
                                                       int N, int K) {
    constexpr int NTN = BN / 32;          // nt per warp (8 or 4)
    constexpr int PB  = BN / 64;          // B ldsm tiles per warp (4 or 2)
    constexpr int BSTGt = BN * GAST;
    constexpr int SBOFFt = 4 * ASTG;
    constexpr int SH  = (BN == 256) ? 0 : 1;
    constexpr int NCH = 4 >> SH;          // B cp.async chunks per thread

    extern __shared__ float gsm[];
    uint32_t sbase = smem_u32(gsm);

    int tid = threadIdx.x;
    int wid = tid >> 5, lane = tid & 31;
    int g = lane >> 2, tg = lane & 3;
    int wm = (wid & 1) * 64;
    int wn = (wid >> 1) * (BN / 4);
    int bn = blockIdx.x * BN;
    int bm = blockIdx.y * 128;
    const int NT = K / GKT;

    int rowA = tid >> 1;
    int cp2 = (tid & 1) * 2;
    const float* Ag = A + (size_t)(bm + rowA) * K + cp2 * 4;
    uint32_t sa0 = sbase + (uint32_t)(rowA * GAST + cp2 * 4) * 4u;

    int rowB = tid >> SH;
    int colB = (tid & ((1 << SH) - 1)) * 8;
    const float* Bg = Bm + (size_t)(bn + rowB) * K + colB;
    uint32_t sb0 = sbase + (uint32_t)(SBOFFt + rowB * GAST + colB) * 4u;

    int lm = lane >> 3, lr8 = lane & 7;
    uint32_t a_lm = sbase + (uint32_t)(((wm + lr8 + (lm & 1) * 8) * GAST + (lm >> 1) * 4) * 4);
    uint32_t b_lm = sbase + (uint32_t)((SBOFFt + (wn + lr8 + (lm >> 1) * 8) * GAST + (lm & 1) * 4) * 4);

#define ISSUE(kt_) do { \
        uint32_t sa_ = (uint32_t)((kt_) & 3) * (ASTG * 4u); \
        uint32_t sb_ = (uint32_t)((kt_) & 3) * (BSTGt * 4u); \
        const float* ga_ = Ag + (kt_) * GKT; \
        const float* gb_ = Bg + (kt_) * GKT; \
        CPA16(sa0 + sa_,        ga_); \
        CPA16(sa0 + sa_ + 16u,  ga_ + 4); \
        _Pragma("unroll") \
        for (int j_ = 0; j_ < NCH; j_++) \
            CPA16(sb0 + sb_ + j_ * 16u, gb_ + j_ * 4); \
        CPCOMMIT(); \
    } while (0)

    float acc[4][NTN][4];
#pragma unroll
    for (int mt = 0; mt < 4; mt++)
#pragma unroll
        for (int nt = 0; nt < NTN; nt++)
#pragma unroll
            for (int q = 0; q < 4; q++) acc[mt][nt][q] = 0.0f;

    ISSUE(0); ISSUE(1); ISSUE(2);

    for (int kt = 0; kt < NT; kt++) {
        asm volatile("cp.async.wait_group 2;" ::: "memory");
        __syncthreads();
        uint32_t saoff = (uint32_t)(kt & 3) * (ASTG * 4u);
        uint32_t sboff = (uint32_t)(kt & 3) * (BSTGt * 4u);
#pragma unroll
        for (int kk = 0; kk < GKT; kk += 8) {
            uint32_t af[4][4], bfm[PB][4];
#pragma unroll
            for (int mt = 0; mt < 4; mt++)
                LDSM4(af[mt], a_lm + saoff + (uint32_t)((mt * 16 * GAST + kk) * 4));
#pragma unroll
            for (int p = 0; p < PB; p++)
                LDSM4(bfm[p], b_lm + sboff + (uint32_t)((p * 16 * GAST + kk) * 4));
#pragma unroll
            for (int mt = 0; mt < 4; mt++)
#pragma unroll
                for (int nt = 0; nt < NTN; nt++)
                    mma_tf32(acc[mt][nt], af[mt], &bfm[nt >> 1][(nt & 1) * 2]);
        }
        if (kt + 3 < NT) ISSUE(kt + 3);
        else CPCOMMIT();
    }

#pragma unroll
    for (int mt = 0; mt < 4; mt++) {
        int rowc = bm + wm + mt * 16 + g;
#pragma unroll
        for (int nt = 0; nt < NTN; nt++) {
            int col = bn + wn + nt * 8 + 2 * tg;
            *(float2*)(C + (size_t)rowc * N + col)       = make_float2(acc[mt][nt][0], acc[mt][nt][1]);
            *(float2*)(C + (size_t)(rowc + 8) * N + col) = make_float2(acc[mt][nt][2], acc[mt][nt][3]);
        }
    }
#undef ISSUE
}

// ============================================================
// RoPE + split. Q/K packed bf16 hi/lo (Q pre-scaled 1/8); V plain fp32.
// ============================================================
__global__ __launch_bounds__(256) void rope_split(const int* __restrict__ pos_ids) {
    int idx = blockIdx.x * blockDim.x + threadIdx.x;
    int i = idx & 31;                 // pair index p
    int rest = idx >> 5;
    int h = rest & 15;
    int rest2 = rest >> 4;
    int s = rest2 % 3;
    int bl = rest2 / 3;

    const float2 e = *(const float2*)(g_qkv + (size_t)bl * E3 + (s * H_ + h) * DH + 2 * i);

    int b = bl >> 11;
    int l = bl & (L_ - 1);
    size_t bh_row = (size_t)(b * H_ + h) * L_ + l;

    if (s == 2) {
        *(float2*)(g_v + bh_row * DH + 2 * i) = e;
    } else {
        float pos = (float)pos_ids[bl];
        float invf = powf(10000.0f, -(float)i * (1.0f / 32.0f));
        float ang = pos * invf;
        float cs, sn;
        sincosf(ang, &sn, &cs);
        float rx = e.x * cs - e.y * sn;
        float ry = e.x * sn + e.y * cs;
        if (s == 0) { rx *= 0.125f; ry *= 0.125f; }
        float hx = bfv(rx), hy = bfv(ry);
        uint32_t hw = packbf(rx, ry);
        uint32_t lw = packbf(rx - hx, ry - hy);
        int w = (i >> 3) * 16 + (i & 3) * 4 + ((i >> 2) & 1) * 2;
        uint32_t* dst = (s == 0 ? g_qhl : g_khl) + bh_row * 64;
        *(uint2*)(dst + w) = make_uint2(hw, lw);
    }
}

// ============================================================
// V transpose + bf16 hi/lo pack: g_v [bh][l][d] -> g_vhl [bh][d][l-words]
// word pattern per 64-seq tile identical to K's pair pattern.
// ============================================================
__global__ __launch_bounds__(128) void v_pack() {
    __shared__ float ts[64][65];
    int lt = blockIdx.x, bh = blockIdx.y;
    int tid = threadIdx.x;

    const float* src = g_v + ((size_t)bh * L_ + lt * 64) * DH;
#pragma unroll
    for (int it = 0; it < 8; it++) {
        int idx = it * 128 + tid;
        int r = idx >> 4, c4 = (idx & 15) * 4;
        float4 v = *(const float4*)(src + r * DH + c4);
        ts[r][c4] = v.x; ts[r][c4 + 1] = v.y; ts[r][c4 + 2] = v.z; ts[r][c4 + 3] = v.w;
    }
    __syncthreads();

    int d = tid >> 1, half = tid & 1;
    uint32_t* dst = g_vhl + ((size_t)bh * 64 + d) * L_ + lt * 64;
#pragma unroll
    for (int pp = 0; pp < 16; pp++) {
        int p = half * 16 + pp;
        float v0 = ts[2 * p][d], v1 = ts[2 * p + 1][d];
        float h0 = bfv(v0), h1 = bfv(v1);
        uint32_t hw = packbf(v0, v1);
        uint32_t lw = packbf(v0 - h0, v1 - h1);
        int w = (p >> 3) * 16 + (p & 3) * 4 + ((p >> 2) & 1) * 2;
        *(uint2*)(dst + w) = make_uint2(hw, lw);
    }
}

// ============================================================
// Tensor-core causal flash attention, all-bf16-3x.
// QK^T: 3xBF16 (Q frags in regs, K 2-stage cp.async).
// PV:   3xBF16, P fragments built IN-LANE (no smem round trip),
//       V^T bf16 hi/lo tiles consumed via one LDS.128 per fragment.
// smem: K[2][64][80]w + V[64][80]w = 61440 B -> 3 CTAs/SM.
// ============================================================
#define KROW 80
#define VROW 80
#define KSTG (64*KROW)              // 5120 words per K stage
#define AVOFF (2*KSTG)              // 10240 words
#define ATT_SMEM ((AVOFF + 64*VROW)*4)  // 61440 B

__global__ __launch_bounds__(128, 3) void attn_tc() {
    extern __shared__ float sm[];
    uint32_t sbase = smem_u32(sm);

    int qt = gridDim.x - 1 - blockIdx.x;   // heavy tiles first
    int bh = blockIdx.y;
    int tid = threadIdx.x;
    int wid = tid >> 5, lane = tid & 31;
    int g = lane >> 2, tg = lane & 3;
    int rowb = wid * 16;

    const uint32_t* Kg = g_khl + (size_t)bh * L_ * 64;
    const uint32_t* Vg = g_vhl + (size_t)bh * 64 * L_;

    // ---- Q bf16 hi/lo fragments straight from global ----
    uint32_t qh[4][4], ql[4][4];
    {
        const uint32_t* Qg = g_qhl + ((size_t)bh * L_ + qt * 64) * 64;
#pragma unroll
        for (int c = 0; c < 4; c++) {
            uint4 t0 = *(const uint4*)(Qg + (rowb + g) * 64 + c * 16 + tg * 4);
            uint4 t1 = *(const uint4*)(Qg + (rowb + 8 + g) * 64 + c * 16 + tg * 4);
            qh[c][0] = t0.x; ql[c][0] = t0.y;
            qh[c][1] = t1.x; ql[c][1] = t1.y;
            qh[c][2] = t0.z; ql[c][2] = t0.w;
            qh[c][3] = t1.z; ql[c][3] = t1.w;
        }
    }

#define KISSUE(j_) do { \
        const uint32_t* Kb_ = Kg + (size_t)(j_) * 64 * 64; \
        uint32_t kd_ = sbase + (uint32_t)(((j_) & 1) * KSTG) * 4u; \
        _Pragma("unroll") \
        for (int it = 0; it < 8; it++) { \
            int lin = it * 128 + tid; \
            int r_ = lin >> 4, ch_ = lin & 15; \
            CPA16(kd_ + (uint32_t)((r_ * KROW + ch_ * 4) * 4), Kb_ + r_ * 64 + ch_ * 4); \
        } \
        CPCOMMIT(); \
    } while (0)
#define VISSUE(j_) do { \
        _Pragma("unroll") \
        for (int it = 0; it < 8; it++) { \
            int lin = it * 128 + tid; \
            int r_ = lin >> 4, ch_ = lin & 15; \
            CPA16(sbase + (uint32_t)((AVOFF + r_ * VROW + ch_ * 4) * 4), \
                  Vg + (size_t)r_ * L_ + (j_) * 64 + ch_ * 4); \
        } \
        CPCOMMIT(); \
    } while (0)

    float o[8][4];
#pragma unroll
    for (int nt = 0; nt < 8; nt++)
#pragma unroll
        for (int q = 0; q < 4; q++) o[nt][q] = 0.0f;
    float mr0 = -1e30f, mr1 = -1e30f, lw0 = 0.0f, lw1 = 0.0f;

    KISSUE(0); VISSUE(0); KISSUE(1);

    for (int jt = 0; jt <= qt; jt++) {
        asm volatile("cp.async.wait_group 1;" ::: "memory");
        __syncthreads();
        const uint32_t* kbs = (const uint32_t*)sm + (jt & 1) * KSTG;
        const uint32_t* vbs = (const uint32_t*)sm + AVOFF;

        // ---- S = Q K^T (3xBF16) ----
        float s[8][4];
#pragma unroll
        for (int nt = 0; nt < 8; nt++)
#pragma unroll
            for (int q = 0; q < 4; q++) s[nt][q] = 0.0f;

#pragma unroll
        for (int c = 0; c < 4; c++) {
#pragma unroll
            for (int nt = 0; nt < 8; nt++) {
                uint4 bq = *(const uint4*)(kbs + (nt * 8 + g) * KROW + c * 16 + tg * 4);
                uint32_t bhv[2] = {bq.x, bq.z};
                uint32_t blv[2] = {bq.y, bq.w};
                mma_bf16(s[nt], qh[c], bhv);
                mma_bf16(s[nt], ql[c], bhv);
                mma_bf16(s[nt], qh[c], blv);
            }
        }

        if (jt == qt) {
            int r0 = rowb + g, r1 = rowb + 8 + g;
#pragma unroll
            for (int nt = 0; nt < 8; nt++) {
                int c0 = nt * 8 + 2 * tg;
                if (c0     > r0) s[nt][0] = -1e30f;
                if (c0 + 1 > r0) s[nt][1] = -1e30f;
                if (c0     > r1) s[nt][2] = -1e30f;
                if (c0 + 1 > r1) s[nt][3] = -1e30f;
            }
        }

        // ---- online softmax ----
        float mx0 = -1e30f, mx1 = -1e30f;
#pragma unroll
        for (int nt = 0; nt < 8; nt++) {
            mx0 = fmaxf(mx0, fmaxf(s[nt][0], s[nt][1]));
            mx1 = fmaxf(mx1, fmaxf(s[nt][2], s[nt][3]));
        }
        mx0 = fmaxf(mx0, __shfl_xor_sync(0xffffffffu, mx0, 1));
        mx0 = fmaxf(mx0, __shfl_xor_sync(0xffffffffu, mx0, 2));
        mx1 = fmaxf(mx1, __shfl_xor_sync(0xffffffffu, mx1, 1));
        mx1 = fmaxf(mx1, __shfl_xor_sync(0xffffffffu, mx1, 2));
        float mn0 = fmaxf(mr0, mx0), mn1 = fmaxf(mr1, mx1);
        float cr0 = __expf(mr0 - mn0), cr1 = __expf(mr1 - mn1);
        float sum0 = 0.0f, sum1 = 0.0f;
#pragma unroll
        for (int nt = 0; nt < 8; nt++) {
            s[nt][0] = __expf(s[nt][0] - mn0);
            s[nt][1] = __expf(s[nt][1] - mn0);
            s[nt][2] = __expf(s[nt][2] - mn1);
            s[nt][3] = __expf(s[nt][3] - mn1);
            sum0 += s[nt][0] + s[nt][1];
            sum1 += s[nt][2] + s[nt][3];
        }
        sum0 += __shfl_xor_sync(0xffffffffu, sum0, 1);
        sum0 += __shfl_xor_sync(0xffffffffu, sum0, 2);
        sum1 += __shfl_xor_sync(0xffffffffu, sum1, 1);
        sum1 += __shfl_xor_sync(0xffffffffu, sum1, 2);
        lw0 = lw0 * cr0 + sum0;
        lw1 = lw1 * cr1 + sum1;
        mr0 = mn0; mr1 = mn1;
#pragma unroll
        for (int nt = 0; nt < 8; nt++) {
            o[nt][0] *= cr0; o[nt][1] *= cr0;
            o[nt][2] *= cr1; o[nt][3] *= cr1;
        }

        // ---- O += P V (3xBF16; P fragments built in-lane, no smem) ----
#pragma unroll
        for (int c = 0; c < 4; c++) {
            uint32_t ph[4], pl[4];
            uint32_t u0 = __float_as_uint(s[2 * c][0]);
            uint32_t u1 = __float_as_uint(s[2 * c][1]);
            uint32_t u2 = __float_as_uint(s[2 * c][2]);
            uint32_t u3 = __float_as_uint(s[2 * c][3]);
            uint32_t u4 = __float_as_uint(s[2 * c + 1][0]);
            uint32_t u5 = __float_as_uint(s[2 * c + 1][1]);
            uint32_t u6 = __float_as_uint(s[2 * c + 1][2]);
            uint32_t u7 = __float_as_uint(s[2 * c + 1][3]);
            ph[0] = __byte_perm(u0, u1, 0x7632);
            ph[1] = __byte_perm(u2, u3, 0x7632);
            ph[2] = __byte_perm(u4, u5, 0x7632);
            ph[3] = __byte_perm(u6, u7, 0x7632);
            pl[0] = packbf(s[2*c][0]   - __uint_as_float(u0 & 0xFFFF0000u),
                           s[2*c][1]   - __uint_as_float(u1 & 0xFFFF0000u));
            pl[1] = packbf(s[2*c][2]   - __uint_as_float(u2 & 0xFFFF0000u),
                           s[2*c][3]   - __uint_as_float(u3 & 0xFFFF0000u));
            pl[2] = packbf(s[2*c+1][0] - __uint_as_float(u4 & 0xFFFF0000u),
                           s[2*c+1][1] - __uint_as_float(u5 & 0xFFFF0000u));
            pl[3] = packbf(s[2*c+1][2] - __uint_as_float(u6 & 0xFFFF0000u),
                           s[2*c+1][3] - __uint_as_float(u7 & 0xFFFF0000u));
#pragma unroll
            for (int nt = 0; nt < 8; nt++) {
                uint4 bq = *(const uint4*)(vbs + (nt * 8 + g) * VROW + c * 16 + tg * 4);
                uint32_t bhv[2] = {bq.x, bq.z};
                uint32_t blv[2] = {bq.y, bq.w};
                mma_bf16(o[nt], ph, bhv);
                mma_bf16(o[nt], pl, bhv);
                mma_bf16(o[nt], ph, blv);
            }
        }

        __syncthreads();   // all reads of K(jt)/V(jt) done before overwrites
        if (jt + 1 <= qt) VISSUE(jt + 1); else CPCOMMIT();
        if (jt + 2 <= qt) KISSUE(jt + 2); else CPCOMMIT();
    }

    // epilogue (tf32-rounded -> feeds out-proj GEMM)
    float i0 = 1.0f / lw0, i1 = 1.0f / lw1;
    int b = bh >> 4, h = bh & 15;
    int r0 = qt * 64 + rowb + g, r1 = r0 + 8;
#pragma unroll
    for (int nt = 0; nt < 8; nt++) {
        int col = h * DH + nt * 8 + 2 * tg;
        *(float2*)(g_ao + (size_t)(b * L_ + r0) * D_ + col) =
            make_float2(tfv(o[nt][0] * i0), tfv(o[nt][1] * i0));
        *(float2*)(g_ao + (size_t)(b * L_ + r1) * D_ + col) =
            make_float2(tfv(o[nt][2] * i1), tfv(o[nt][3] * i1));
    }
#undef KISSUE
#undef VISSUE
}

// ============================================================
extern "C" void kernel_launch(void* const* d_in, const int* in_sizes, int n_in,
                              void* d_out, int out_size) {
    const float* x    = (const float*)d_in[0];
    const float* Wqkv = (const float*)d_in[1];
    const float* Wout = (const float*)d_in[2];
    const int*   pos  = (const int*)d_in[3];
    float* out = (float*)d_out;

    float *p_qkv, *p_ao, *p_xc, *p_wq, *p_wo;
    cudaGetSymbolAddress((void**)&p_qkv, g_qkv);
    cudaGetSymbolAddress((void**)&p_ao, g_ao);
    cudaGetSymbolAddress((void**)&p_xc, g_xc);
    cudaGetSymbolAddress((void**)&p_wq, g_wq);
    cudaGetSymbolAddress((void**)&p_wo, g_wo);

    const int GS256 = (4 * ASTG + 4 * 256 * GAST) * 4;   // 122880
    const int GS128 = (4 * ASTG + 4 * 128 * GAST) * 4;   // 81920
    cudaFuncSetAttribute(attn_tc, cudaFuncAttributeMaxDynamicSharedMemorySize, ATT_SMEM);
    cudaFuncSetAttribute(gemm_ca<256, 1>, cudaFuncAttributeMaxDynamicSharedMemorySize, GS256);
    cudaFuncSetAttribute(gemm_ca<128, 2>, cudaFuncAttributeMaxDynamicSharedMemorySize, GS128);

    // 0) pre-convert operands to tf32
    conv_tf32<<<(BL * D_ / 4 + 255) / 256, 256>>>((const float4*)x, (float4*)p_xc, BL * D_ / 4);
    conv_tf32<<<(E3 * D_ / 4 + 255) / 256, 256>>>((const float4*)Wqkv, (float4*)p_wq, E3 * D_ / 4);
    conv_tf32<<<(D_ * D_ / 4 + 255) / 256, 256>>>((const float4*)Wout, (float4*)p_wo, D_ * D_ / 4);

    // 1) qkv = x @ W_qkv^T
    gemm_ca<256, 1><<<dim3(E3 / 256, BL / 128), 256, GS256>>>(p_xc, p_wq, p_qkv, E3, D_);
    // 2) rope + split -> qhl/khl (bf16 hi/lo) + v (fp32)
    rope_split<<<(BL * E3 / 2) / 256, 256>>>(pos);
    // 2b) V transpose + bf16 hi/lo pack
    v_pack<<<dim3(L_ / 64, B_ * H_), 128>>>();
    // 3) tensor-core causal flash attention -> g_ao (tf32)
    attn_tc<<<dim3(L_ / 64, B_ * H_), 128, ATT_SMEM>>>();
    // 4) out = g_ao @ W_out^T
    gemm_ca<128, 2><<<dim3(D_ / 128, BL / 128), 256, GS128>>>(p_ao, p_wo, out, D_, D_);
}